// round 3
// baseline (speedup 1.0000x reference)
#include <cuda_runtime.h>
#include <cstdint>

// out[pid] = verified_id[nd * pid + accept_lens[pid] - 1]
// bs = out_size (2,097,152), nd = in_sizes[0] / out_size (16).
// accept_lens is int32 (JAX x64-disabled downcasts the requested int64).
// Each thread handles 4 pids: int4 lens load, 4 independent gathers in
// flight, float4 store.

__global__ void gather_verified_x4(const float* __restrict__ verified_id,
                                   const int* __restrict__ accept_lens,
                                   float* __restrict__ out,
                                   int bs_quads,   // bs / 4
                                   int nd) {
    int t = blockIdx.x * blockDim.x + threadIdx.x;
    if (t >= bs_quads) return;

    const int4 lens = reinterpret_cast<const int4*>(accept_lens)[t];
    long long base = (long long)nd * (4LL * t);

    float v0 = __ldg(verified_id + base + (lens.x - 1));
    float v1 = __ldg(verified_id + base + nd + (lens.y - 1));
    float v2 = __ldg(verified_id + base + 2LL * nd + (lens.z - 1));
    float v3 = __ldg(verified_id + base + 3LL * nd + (lens.w - 1));

    reinterpret_cast<float4*>(out)[t] = make_float4(v0, v1, v2, v3);
}

// Scalar fallback for bs not divisible by 4 (not expected here).
__global__ void gather_verified_scalar(const float* __restrict__ verified_id,
                                       const int* __restrict__ accept_lens,
                                       float* __restrict__ out,
                                       int bs, int nd) {
    int pid = blockIdx.x * blockDim.x + threadIdx.x;
    if (pid >= bs) return;
    long long idx = (long long)nd * pid + accept_lens[pid] - 1;
    out[pid] = __ldg(verified_id + idx);
}

extern "C" void kernel_launch(void* const* d_in, const int* in_sizes, int n_in,
                              void* d_out, int out_size) {
    const float* verified_id = (const float*)d_in[0];
    const int* accept_lens = (const int*)d_in[1];
    float* out = (float*)d_out;

    int bs = out_size;
    int nd = in_sizes[0] / out_size;  // = num_draft_tokens (16)

    if ((bs & 3) == 0) {
        int quads = bs / 4;
        int threads = 256;
        int blocks = (quads + threads - 1) / threads;
        gather_verified_x4<<<blocks, threads>>>(verified_id, accept_lens, out,
                                                quads, nd);
    } else {
        int threads = 256;
        int blocks = (bs + threads - 1) / threads;
        gather_verified_scalar<<<blocks, threads>>>(verified_id, accept_lens, out,
                                                    bs, nd);
    }
}